// round 17
// baseline (speedup 1.0000x reference)
#include <cuda_runtime.h>
#include <cuda_bf16.h>
#include <cstdint>

#define NJ     32
#define TPB    32                    // single warp per CTA
#define BPB    32                    // one batch (record) per lane
#define RECW   292                   // 288 + 4 pad words; addr16 stride 73 = 1 mod 8
                                     //  -> conflict-free LDS.128 / STS.128
#define IN_WORDS  (BPB * RECW)       // 9344 words
#define MBAR_WORD IN_WORDS
#define SMEM_BYTES (MBAR_WORD * 4 + 16)   // 37,392 B -> 6 CTAs/SM
#define GRID   888                   // 148 SMs x 6 resident CTAs, persistent

#define HALF_BYTES 576u              // 36 float4 = groups 0-3 (or 4-7)

// ---------------- async-engine primitives (1D bulk, no tensor map) ----------
__device__ __forceinline__ void mbar_init(uint32_t mb, uint32_t cnt) {
    asm volatile("mbarrier.init.shared::cta.b64 [%0], %1;" :: "r"(mb), "r"(cnt));
}
__device__ __forceinline__ void mbar_expect(uint32_t mb, uint32_t bytes) {
    asm volatile("mbarrier.arrive.expect_tx.shared::cta.b64 _, [%0], %1;"
                 :: "r"(mb), "r"(bytes) : "memory");
}
__device__ __forceinline__ void bulk_ld(uint32_t sdst, const void* gsrc,
                                        uint32_t bytes, uint32_t mb) {
    asm volatile("cp.async.bulk.shared::cta.global.mbarrier::complete_tx::bytes "
                 "[%0], [%1], %2, [%3];"
                 :: "r"(sdst), "l"(gsrc), "r"(bytes), "r"(mb) : "memory");
}
__device__ __forceinline__ void bulk_st(void* gdst, uint32_t ssrc, uint32_t bytes) {
    asm volatile("cp.async.bulk.global.shared::cta.bulk_group [%0], [%1], %2;"
                 :: "l"(gdst), "r"(ssrc), "r"(bytes) : "memory");
}
__device__ __forceinline__ void bulk_st_commit() {
    asm volatile("cp.async.bulk.commit_group;" ::: "memory");
}
__device__ __forceinline__ void bulk_st_wait_read0() {
    asm volatile("cp.async.bulk.wait_group.read 0;" ::: "memory");
}
__device__ __forceinline__ void fence_async() {
    asm volatile("fence.proxy.async.shared::cta;" ::: "memory");
}
__device__ __forceinline__ void mwait(uint32_t mb, uint32_t phase) {
    uint32_t done;
    asm volatile("{\n\t.reg .pred p;\n\t"
                 "mbarrier.try_wait.parity.acquire.cta.shared::cta.b64 p, [%1], %2;\n\t"
                 "selp.b32 %0, 1, 0, p;\n\t}"
                 : "=r"(done) : "r"(mb), "r"(phase) : "memory");
    if (!done) {
        asm volatile("{\n\t.reg .pred P1;\n\t"
                     "W%=:\n\t"
                     "mbarrier.try_wait.parity.acquire.cta.shared::cta.b64 P1, [%0], %1, 0x989680;\n\t"
                     "@P1 bra.uni D%=;\n\t"
                     "bra.uni W%=;\n\t"
                     "D%=:\n\t}"
                     :: "r"(mb), "r"(phase) : "memory");
    }
}

__global__ void __launch_bounds__(TPB)
fk32_kernel(const float* __restrict__ angles,
            const float* __restrict__ offs,
            float* __restrict__ out,
            int batch)
{
    extern __shared__ float s[];
    const int t   = threadIdx.x;
    const int bid = blockIdx.x;
    const uint32_t sbase = (uint32_t)__cvta_generic_to_shared(s);

    const uint32_t mbA = sbase + (uint32_t)MBAR_WORD * 4u;
    const uint32_t mbB = mbA + 8u;
    const uint32_t inrow = sbase + (uint32_t)(t * RECW) * 4u;   // lane's record row

    const int ntiles = (batch + BPB - 1) / BPB;        // 8192
    if (bid >= ntiles) return;

    if (t == 0) { mbar_init(mbA, TPB); mbar_init(mbB, TPB); }
    __syncwarp();
    fence_async();          // publish barrier init to the async proxy

    const int par[NJ] = {-1,0,1,2,3,4,0,6,7,8,9,0,11,12,13,14,12,16,17,18,
                         19,20,19,22,12,24,25,26,27,28,27,30};
    const bool isp[NJ] = {1,1,1,1,1,0,1,1,1,1,0,1,1,1,1,0,
                          1,1,1,1,1,0,1,0,1,1,1,1,1,0,1,0};

    // lane's record byte address for tile `tl`
    auto grec = [&](int tl) -> const char* {
        long r = (long)tl * BPB + t;
        if (r >= batch) r = batch - 1;          // safe clamp (exact tiles here)
        return reinterpret_cast<const char*>(angles) + (size_t)r * 1152u;
    };

    // ---- prologue: both halves of first tile in flight ---------------------
    mbar_expect(mbA, HALF_BYTES);
    bulk_ld(inrow, grec(bid), HALF_BYTES, mbA);
    mbar_expect(mbB, HALF_BYTES);
    bulk_ld(inrow + HALF_BYTES, grec(bid) + HALF_BYTES, HALF_BYTES, mbB);

    float R[NJ][9];
    float P[NJ][3];
    const float4* recv = reinterpret_cast<const float4*>(s + t * RECW);
    float4*       pv   = reinterpret_cast<float4*>(s + t * RECW);   // in-place pack

    uint32_t pa = 0, pb = 0;

    for (int tile = bid; tile < ntiles; tile += GRID) {
        const int  nxt  = tile + GRID;
        const bool more = (nxt < ntiles);
        const long rrec = (long)tile * BPB + t;

        // ================= half A: groups 0..3 =============================
        mwait(mbA, pa); pa ^= 1;          // bytes [0,576) of my record landed

        #pragma unroll
        for (int g = 0; g < 4; ++g) {
            float a[36];
            #pragma unroll
            for (int q = 0; q < 9; ++q) {
                float4 v = recv[g * 9 + q];
                a[4*q+0] = v.x; a[4*q+1] = v.y; a[4*q+2] = v.z; a[4*q+3] = v.w;
            }
            #pragma unroll
            for (int jj = 0; jj < 4; ++jj) {
                const int j = g * 4 + jj;
                const float* Aj = &a[jj * 9];
                if (j == 0) {
                    #pragma unroll
                    for (int q = 0; q < 9; ++q) R[0][q] = Aj[q];
                    P[0][0] = 0.f; P[0][1] = 0.f; P[0][2] = 0.f;
                } else {
                    const int p = par[j];
                    const float o0 = __ldg(&offs[j*3+0]);
                    const float o1 = __ldg(&offs[j*3+1]);
                    const float o2 = __ldg(&offs[j*3+2]);
                    #pragma unroll
                    for (int l = 0; l < 3; ++l) {
                        P[j][l] = fmaf(o0, R[p][0*3+l],
                                  fmaf(o1, R[p][1*3+l],
                                  fmaf(o2, R[p][2*3+l], P[p][l])));
                    }
                    if (isp[j]) {
                        #pragma unroll
                        for (int i = 0; i < 3; ++i) {
                            #pragma unroll
                            for (int l = 0; l < 3; ++l) {
                                R[j][i*3+l] = fmaf(Aj[i*3+0], R[p][0*3+l],
                                              fmaf(Aj[i*3+1], R[p][1*3+l],
                                                   Aj[i*3+2] * R[p][2*3+l]));
                            }
                        }
                    }
                }
            }
            // pack pos of group g into words [12g,12g+12): group g's own data
            // is in regs; later slots sit in already-consumed earlier groups.
            const int j0 = g * 4;
            pv[g*3+0] = make_float4(P[j0+0][0], P[j0+0][1], P[j0+0][2], P[j0+1][0]);
            pv[g*3+1] = make_float4(P[j0+1][1], P[j0+1][2], P[j0+2][0], P[j0+2][1]);
            pv[g*3+2] = make_float4(P[j0+2][2], P[j0+3][0], P[j0+3][1], P[j0+3][2]);
        }

        // store pos A (words [0,48) = 192B), then refill half A for next tile
        fence_async();                    // order STS before async-proxy read
        if (rrec < batch) bulk_st(out + (size_t)rrec * 96u, inrow, 192u);
        bulk_st_commit();
        bulk_st_wait_read0();             // smem read done -> safe to overwrite
        if (more) {
            mbar_expect(mbA, HALF_BYTES);
            bulk_ld(inrow, grec(nxt), HALF_BYTES, mbA);
        }

        // ================= half B: groups 4..7 =============================
        mwait(mbB, pb); pb ^= 1;

        #pragma unroll
        for (int g = 4; g < 8; ++g) {
            float a[36];
            #pragma unroll
            for (int q = 0; q < 9; ++q) {
                float4 v = recv[g * 9 + q];
                a[4*q+0] = v.x; a[4*q+1] = v.y; a[4*q+2] = v.z; a[4*q+3] = v.w;
            }
            #pragma unroll
            for (int jj = 0; jj < 4; ++jj) {
                const int j = g * 4 + jj;
                const float* Aj = &a[jj * 9];
                const int p = par[j];
                const float o0 = __ldg(&offs[j*3+0]);
                const float o1 = __ldg(&offs[j*3+1]);
                const float o2 = __ldg(&offs[j*3+2]);
                #pragma unroll
                for (int l = 0; l < 3; ++l) {
                    P[j][l] = fmaf(o0, R[p][0*3+l],
                              fmaf(o1, R[p][1*3+l],
                              fmaf(o2, R[p][2*3+l], P[p][l])));
                }
                if (isp[j]) {
                    #pragma unroll
                    for (int i = 0; i < 3; ++i) {
                        #pragma unroll
                        for (int l = 0; l < 3; ++l) {
                            R[j][i*3+l] = fmaf(Aj[i*3+0], R[p][0*3+l],
                                          fmaf(Aj[i*3+1], R[p][1*3+l],
                                               Aj[i*3+2] * R[p][2*3+l]));
                        }
                    }
                }
            }
            // pack pos of group g into words [144+(g-4)*12, ...+12): inside
            // g4/g5 data words, all consumed by the time each pack happens.
            pv[36 + (g - 4) * 3 + 0] =
                make_float4(P[g*4+0][0], P[g*4+0][1], P[g*4+0][2], P[g*4+1][0]);
            pv[36 + (g - 4) * 3 + 1] =
                make_float4(P[g*4+1][1], P[g*4+1][2], P[g*4+2][0], P[g*4+2][1]);
            pv[36 + (g - 4) * 3 + 2] =
                make_float4(P[g*4+2][2], P[g*4+3][0], P[g*4+3][1], P[g*4+3][2]);
        }

        // store pos B (words [144,192) = 192B), then refill half B
        fence_async();
        if (rrec < batch) bulk_st(out + (size_t)rrec * 96u + 48u, inrow + 576u, 192u);
        bulk_st_commit();
        bulk_st_wait_read0();
        if (more) {
            mbar_expect(mbB, HALF_BYTES);
            bulk_ld(inrow + HALF_BYTES, grec(nxt) + HALF_BYTES, HALF_BYTES, mbB);
        }
    }
    bulk_st_wait_read0();                 // drain before exit
}

extern "C" void kernel_launch(void* const* d_in, const int* in_sizes, int n_in,
                              void* d_out, int out_size)
{
    const float* angles = (const float*)d_in[0];
    const float* offs   = (const float*)d_in[1];
    float* out          = (float*)d_out;

    int batch = in_sizes[0] / (NJ * 9);                // 262144

    static bool attr_done = false;
    if (!attr_done) {
        cudaFuncSetAttribute(fk32_kernel,
                             cudaFuncAttributeMaxDynamicSharedMemorySize,
                             SMEM_BYTES);
        attr_done = true;
    }

    fk32_kernel<<<GRID, TPB, SMEM_BYTES>>>(angles, offs, out, batch);
}